// round 4
// baseline (speedup 1.0000x reference)
#include <cuda_runtime.h>
#include <cstdint>

#define DIN     16
#define DOUT    99
#define CH      128
#define MAXNNZ  512
#define EPB     2          // edges per block
#define TPB     256        // 8 warps: 4 warps per edge (m3-chunked)
#define NCHUNK  4

// Single fused kernel: warp 0 builds sorted metadata (deterministic counting
// sort by mu3 via match_any ranks) while warps 1-7 stage x/y tiles. Then all
// 8 warps run the segmented contraction with packed f32x2 FMAs.
__global__ void __launch_bounds__(TPB) tp_kernel(const float* __restrict__ x,
                                                 const float* __restrict__ y,
                                                 const int*   __restrict__ mu1,
                                                 const int*   __restrict__ mu2,
                                                 const int*   __restrict__ mu3,
                                                 const float* __restrict__ cg,
                                                 float* __restrict__ out,
                                                 int nnz)
{
    __shared__ float      sx[EPB * DIN * CH];
    __shared__ float      sy[EPB * DIN * CH];
    __shared__ ulonglong2 s_meta[MAXNNZ];      // {off1|off2<<32, cg|cg<<32}
    __shared__ int        s_mu3[MAXNNZ];
    __shared__ int        s_rk[MAXNNZ];
    __shared__ int        s_run[DOUT];
    __shared__ int        s_start[DOUT + 1];
    __shared__ int        s_cm3[NCHUNK + 1];

    const int tid  = threadIdx.x;
    const int wid  = tid >> 5;
    const int lane = tid & 31;
    const int n0   = blockIdx.x * EPB;
    if (nnz > MAXNNZ) nnz = MAXNNZ;

    if (wid == 0) {
        // ---- deterministic counting sort of paths by mu3 (warp 0 only) ----
        for (int i = lane; i < DOUT; i += 32) s_run[i] = 0;
        for (int i = lane; i < nnz;  i += 32) s_mu3[i] = mu3[i];
        __syncwarp();

        for (int base = 0; base < nnz; base += 32) {
            int  k     = base + lane;
            bool valid = k < nnz;
            int  m3    = valid ? s_mu3[k] : (DOUT + lane);   // unique dummies
            unsigned peers  = __match_any_sync(0xffffffffu, m3);
            int      leader = __ffs(peers) - 1;
            int cnt = 0;
            if (valid && lane == leader) cnt = s_run[m3];
            cnt = __shfl_sync(0xffffffffu, cnt, leader);
            if (valid) s_rk[k] = cnt + __popc(peers & ((1u << lane) - 1));
            if (valid && lane == leader) s_run[m3] = cnt + __popc(peers);
            __syncwarp();
        }

        // exclusive scan of counts -> segment starts
        int carry = 0;
        if (lane == 0) s_start[0] = 0;
        #pragma unroll
        for (int r = 0; r < (DOUT + 31) / 32; r++) {
            int idx = r * 32 + lane;
            int v   = (idx < DOUT) ? s_run[idx] : 0;
            #pragma unroll
            for (int d = 1; d < 32; d <<= 1) {
                int t = __shfl_up_sync(0xffffffffu, v, d);
                if (lane >= d) v += t;
            }
            if (idx < DOUT) s_start[idx + 1] = carry + v;
            carry += __shfl_sync(0xffffffffu, v, 31);
        }
        __syncwarp();

        // cost-balanced m3 chunk boundaries (cost = seg len + 2)
        if (lane == 0) { s_cm3[0] = 0; s_cm3[NCHUNK] = DOUT; }
        if (lane >= 1 && lane < NCHUNK) {
            int total  = s_start[DOUT] + 2 * DOUT;
            int target = (total * lane) / NCHUNK;
            int m = 0;
            while (m < DOUT && (s_start[m] + 2 * m) < target) m++;
            s_cm3[lane] = m;
        }
        __syncwarp();

        // scatter packed metadata into sorted order
        for (int k = lane; k < nnz; k += 32) {
            int m3  = s_mu3[k];
            int pos = s_start[m3] + s_rk[k];
            unsigned o1 = (unsigned)(mu1[k] * (CH * 4));   // byte offsets
            unsigned o2 = (unsigned)(mu2[k] * (CH * 4));
            unsigned cb = __float_as_uint(cg[k]);
            ulonglong2 mv;
            mv.x = (unsigned long long)o1 | ((unsigned long long)o2 << 32);
            mv.y = (unsigned long long)cb | ((unsigned long long)cb << 32);
            s_meta[pos] = mv;
        }
    } else {
        // ---- warps 1-7: stage x/y tiles (read-once -> streaming loads) ----
        const int     t   = tid - 32;              // 0..223
        const float4* gx  = (const float4*)(x + (size_t)n0 * DIN * CH);
        const float4* gy  = (const float4*)(y + (size_t)n0 * DIN * CH);
        float4*       sx4 = (float4*)sx;
        float4*       sy4 = (float4*)sy;
        const int NV = EPB * DIN * CH / 4;         // 1024
        for (int i = t; i < NV; i += TPB - 32) {
            sx4[i] = __ldcs(gx + i);
            sy4[i] = __ldcs(gy + i);
        }
    }
    __syncthreads();

    // ---- main contraction: warp w -> edge w>>2, m3 chunk w&3 ----
    const int e     = wid >> 2;
    const int chunk = wid & 3;
    const char* mxc = (const char*)sx + e * (DIN * CH * 4) + lane * 16;
    const char* myc = (const char*)sy + e * (DIN * CH * 4) + lane * 16;
    const int m3lo  = s_cm3[chunk];
    const int m3hi  = s_cm3[chunk + 1];

    int kb = s_start[m3lo];
    float4* dst = (float4*)(out + (size_t)(n0 + e) * DOUT * CH + (size_t)m3lo * CH) + lane;

    for (int m3 = m3lo; m3 < m3hi; m3++) {
        const int ke = s_start[m3 + 1];
        unsigned long long a01 = 0ull, a23 = 0ull;   // two f32x2 accumulators
        for (int k = kb; k < ke; k++) {
            const ulonglong2 me = s_meta[k];
            const ulonglong2 xv = *(const ulonglong2*)(mxc + (unsigned)(me.x & 0xffffffffu));
            const ulonglong2 yv = *(const ulonglong2*)(myc + (unsigned)(me.x >> 32));
            unsigned long long p01, p23;
            asm("mul.rn.f32x2 %0, %1, %2;" : "=l"(p01) : "l"(xv.x), "l"(yv.x));
            asm("mul.rn.f32x2 %0, %1, %2;" : "=l"(p23) : "l"(xv.y), "l"(yv.y));
            asm("fma.rn.f32x2 %0, %1, %2, %3;" : "=l"(a01) : "l"(me.y), "l"(p01), "l"(a01));
            asm("fma.rn.f32x2 %0, %1, %2, %3;" : "=l"(a23) : "l"(me.y), "l"(p23), "l"(a23));
        }
        kb = ke;
        float4 rv;
        asm("mov.b64 {%0, %1}, %4;\n\t"
            "mov.b64 {%2, %3}, %5;"
            : "=f"(rv.x), "=f"(rv.y), "=f"(rv.z), "=f"(rv.w)
            : "l"(a01), "l"(a23));
        __stcs(dst, rv);            // streaming store, bypass L2 retention
        dst += CH / 4;              // next m3 row (contiguous within chunk)
    }
}

// ---------------- launch ----------------
extern "C" void kernel_launch(void* const* d_in, const int* in_sizes, int n_in,
                              void* d_out, int out_size)
{
    const float* x   = (const float*)d_in[0];
    const float* y   = (const float*)d_in[1];
    const int*   mu1 = (const int*)d_in[2];
    const int*   mu2 = (const int*)d_in[3];
    const int*   mu3 = (const int*)d_in[4];
    const float* cg  = (const float*)d_in[5];
    const int    nnz = in_sizes[2];
    const int    n_edges = in_sizes[0] / (DIN * CH);

    float* out = (float*)d_out;

    tp_kernel<<<n_edges / EPB, TPB>>>(x, y, mu1, mu2, mu3, cg, out, nnz);
}

// round 5
// speedup vs baseline: 1.1779x; 1.1779x over previous
#include <cuda_runtime.h>
#include <cstdint>

#define DIN     16
#define DOUT    99
#define CH      128
#define MAXNNZ  384
#define EPB     2          // edges per group
#define TPB     256        // 8 warps: 4 warps per edge (m3-chunked)
#define NCHUNK  4
#define NBLK    740        // 148 SMs * 5 resident blocks (persistent grid)

// ---------------- device scratch (no allocations allowed) ----------------
__device__ ulonglong2 g_meta[MAXNNZ];   // {off1|off2<<32 (bytes), cg|cg<<32}
__device__ int        g_start[DOUT + 1];
__device__ int        g_cm3[NCHUNK + 1];

// ---------------- prep: single-warp deterministic counting sort ----------------
__global__ void prep_kernel(const int* __restrict__ mu1,
                            const int* __restrict__ mu2,
                            const int* __restrict__ mu3,
                            const float* __restrict__ cg,
                            int nnz)
{
    __shared__ int s_mu3[MAXNNZ];
    __shared__ int s_rk[MAXNNZ];
    __shared__ int s_run[DOUT];
    __shared__ int s_start[DOUT + 1];

    const int lane = threadIdx.x;      // 32 threads
    if (nnz > MAXNNZ) nnz = MAXNNZ;

    for (int i = lane; i < DOUT; i += 32) s_run[i] = 0;
    for (int i = lane; i < nnz;  i += 32) s_mu3[i] = mu3[i];
    __syncwarp();

    // deterministic rank within equal-mu3 runs (batch of 32, match_any)
    for (int base = 0; base < nnz; base += 32) {
        int  k     = base + lane;
        bool valid = k < nnz;
        int  m3    = valid ? s_mu3[k] : (DOUT + lane);     // unique dummies
        unsigned peers  = __match_any_sync(0xffffffffu, m3);
        int      leader = __ffs(peers) - 1;
        int cnt = 0;
        if (valid && lane == leader) cnt = s_run[m3];
        cnt = __shfl_sync(0xffffffffu, cnt, leader);
        if (valid) s_rk[k] = cnt + __popc(peers & ((1u << lane) - 1));
        if (valid && lane == leader) s_run[m3] = cnt + __popc(peers);
        __syncwarp();
    }

    // exclusive scan of counts -> segment starts
    int carry = 0;
    if (lane == 0) s_start[0] = 0;
    #pragma unroll
    for (int r = 0; r < (DOUT + 31) / 32; r++) {
        int idx = r * 32 + lane;
        int v   = (idx < DOUT) ? s_run[idx] : 0;
        #pragma unroll
        for (int d = 1; d < 32; d <<= 1) {
            int t = __shfl_up_sync(0xffffffffu, v, d);
            if (lane >= d) v += t;
        }
        if (idx < DOUT) s_start[idx + 1] = carry + v;
        carry += __shfl_sync(0xffffffffu, v, 31);
    }
    __syncwarp();

    for (int i = lane; i <= DOUT; i += 32) g_start[i] = s_start[i];

    // cost-balanced m3 chunk boundaries (cost = seg len + 2)
    if (lane == 0) { g_cm3[0] = 0; g_cm3[NCHUNK] = DOUT; }
    if (lane >= 1 && lane < NCHUNK) {
        int total  = s_start[DOUT] + 2 * DOUT;
        int target = (total * lane) / NCHUNK;
        int m = 0;
        while (m < DOUT && (s_start[m] + 2 * m) < target) m++;
        g_cm3[lane] = m;
    }

    // scatter packed metadata into sorted order
    for (int k = lane; k < nnz; k += 32) {
        int m3  = s_mu3[k];
        int pos = s_start[m3] + s_rk[k];
        unsigned o1 = (unsigned)(mu1[k] * (CH * 4));       // byte offsets
        unsigned o2 = (unsigned)(mu2[k] * (CH * 4));
        unsigned cb = __float_as_uint(cg[k]);
        ulonglong2 mv;
        mv.x = (unsigned long long)o1 | ((unsigned long long)o2 << 32);
        mv.y = (unsigned long long)cb | ((unsigned long long)cb << 32);
        g_meta[pos] = mv;
    }
}

// ---------------- main tensor-product kernel (persistent) ----------------
// 740 blocks, 256 threads. Each block loops over edge-groups of EPB edges.
// Within a group: warp w -> edge w>>2, m3 chunk w&3; lane owns 4 channels.
__global__ void __launch_bounds__(TPB, 5) tp_kernel(const float* __restrict__ x,
                                                    const float* __restrict__ y,
                                                    float* __restrict__ out,
                                                    int nnz, int ngroups)
{
    __shared__ float      sx[EPB * DIN * CH];
    __shared__ float      sy[EPB * DIN * CH];
    __shared__ ulonglong2 s_meta[MAXNNZ];
    __shared__ int        s_start[DOUT + 1];
    __shared__ int        s_cm3[NCHUNK + 1];

    const int tid  = threadIdx.x;
    const int wid  = tid >> 5;
    const int lane = tid & 31;
    if (nnz > MAXNNZ) nnz = MAXNNZ;

    // stage metadata ONCE per block (amortized over all groups)
    for (int i = tid; i < nnz; i += TPB) s_meta[i] = g_meta[i];
    for (int i = tid; i <= DOUT; i += TPB) s_start[i] = g_start[i];
    if (tid <= NCHUNK) s_cm3[tid] = g_cm3[tid];

    const int e     = wid >> 2;        // local edge 0/1
    const int chunk = wid & 3;         // m3 chunk for this warp
    const char* mxc = (const char*)sx + e * (DIN * CH * 4) + lane * 16;
    const char* myc = (const char*)sy + e * (DIN * CH * 4) + lane * 16;

    for (int g = blockIdx.x; g < ngroups; g += NBLK) {
        const int n0 = g * EPB;

        __syncthreads();               // previous group's readers done
        // stage x/y tiles for this group's EPB edges (streaming loads)
        {
            const float4* gx  = (const float4*)(x + (size_t)n0 * DIN * CH);
            const float4* gy  = (const float4*)(y + (size_t)n0 * DIN * CH);
            float4*       sx4 = (float4*)sx;
            float4*       sy4 = (float4*)sy;
            const int NV = EPB * DIN * CH / 4;     // 1024
            #pragma unroll
            for (int i = tid; i < NV; i += TPB) {
                sx4[i] = __ldcs(gx + i);
                sy4[i] = __ldcs(gy + i);
            }
        }
        __syncthreads();

        const int m3lo = s_cm3[chunk];
        const int m3hi = s_cm3[chunk + 1];
        int kb = s_start[m3lo];
        float4* dst = (float4*)(out + (size_t)(n0 + e) * DOUT * CH
                                    + (size_t)m3lo * CH) + lane;

        for (int m3 = m3lo; m3 < m3hi; m3++) {
            const int ke = s_start[m3 + 1];
            unsigned long long a01 = 0ull, a23 = 0ull;   // packed f32x2 accs
            #pragma unroll 2
            for (int k = kb; k < ke; k++) {
                const ulonglong2 me = s_meta[k];
                const ulonglong2 xv = *(const ulonglong2*)(mxc + (unsigned)(me.x & 0xffffffffu));
                const ulonglong2 yv = *(const ulonglong2*)(myc + (unsigned)(me.x >> 32));
                unsigned long long p01, p23;
                asm("mul.rn.f32x2 %0, %1, %2;" : "=l"(p01) : "l"(xv.x), "l"(yv.x));
                asm("mul.rn.f32x2 %0, %1, %2;" : "=l"(p23) : "l"(xv.y), "l"(yv.y));
                asm("fma.rn.f32x2 %0, %1, %2, %3;" : "=l"(a01) : "l"(me.y), "l"(p01), "l"(a01));
                asm("fma.rn.f32x2 %0, %1, %2, %3;" : "=l"(a23) : "l"(me.y), "l"(p23), "l"(a23));
            }
            kb = ke;
            float4 rv;
            asm("mov.b64 {%0, %1}, %4;\n\t"
                "mov.b64 {%2, %3}, %5;"
                : "=f"(rv.x), "=f"(rv.y), "=f"(rv.z), "=f"(rv.w)
                : "l"(a01), "l"(a23));
            __stcs(dst, rv);           // streaming store, bypass L2 retention
            dst += CH / 4;             // next m3 row (contiguous within chunk)
        }
    }
}

// ---------------- launch ----------------
extern "C" void kernel_launch(void* const* d_in, const int* in_sizes, int n_in,
                              void* d_out, int out_size)
{
    const float* x   = (const float*)d_in[0];
    const float* y   = (const float*)d_in[1];
    const int*   mu1 = (const int*)d_in[2];
    const int*   mu2 = (const int*)d_in[3];
    const int*   mu3 = (const int*)d_in[4];
    const float* cg  = (const float*)d_in[5];
    const int    nnz = in_sizes[2];
    const int    n_edges = in_sizes[0] / (DIN * CH);
    const int    ngroups = n_edges / EPB;

    float* out = (float*)d_out;

    prep_kernel<<<1, 32>>>(mu1, mu2, mu3, cg, nnz);
    tp_kernel<<<NBLK, TPB>>>(x, y, out, nnz, ngroups);
}